// round 6
// baseline (speedup 1.0000x reference)
#include <cuda_runtime.h>
#include <cstdint>

#define L0 32
#define DIM 288          // 32 + 96 + 160
#define NRBF 8
#define HID 64
#define NPATHS 7
#define WCOLS 224        // NPATHS * L0
#define NORM 0.25f       // 1/sqrt(16)
#define NMAX 50176
#define TILE_E 64
#define HSTR 68          // h_sm row stride (conflict-free A-frag LDS)
#define WSTR 228         // w_sm row stride

// Scratch (static device globals; no runtime allocation allowed)
__device__ float g_si1[(size_t)NMAX * DIM];
__device__ float g_conv[(size_t)NMAX * DIM];
__device__ uint2 g_Bfrag[28 * 8 * 32];   // Wr2 tf32, mma-fragment order

__device__ __forceinline__ unsigned cvt_tf32(float v) {
    unsigned r;
    asm("cvt.rna.tf32.f32 %0, %1;" : "=r"(r) : "f"(v));
    return r;
}

// ---------------------------------------------------------------------------
// Kernel 0: build tf32 fragment-ordered Wr2 (pre-scaled by NORM)
// ---------------------------------------------------------------------------
__global__ void k_prep(const float* __restrict__ Wr2)
{
    int ntg = blockIdx.x;            // 0..27 (n-tile of 8 cols)
    int t = threadIdx.x;
    int ks = t >> 5;                 // 0..7
    int lane = t & 31;
    int r4 = lane >> 2, c4 = lane & 3;
    int col = ntg * 8 + r4;
    int row0 = ks * 8 + c4;
    uint2 b;
    b.x = cvt_tf32(Wr2[row0 * WCOLS + col] * NORM);
    b.y = cvt_tf32(Wr2[(row0 + 4) * WCOLS + col] * NORM);
    g_Bfrag[(ntg * 8 + ks) * 32 + lane] = b;
}

// ---------------------------------------------------------------------------
// Kernel 1: si1 = irreps_linear(nodes); also zeroes g_conv rows
// ---------------------------------------------------------------------------
__global__ void k_lin1(const float* __restrict__ x,
                       const float* __restrict__ W0,
                       const float* __restrict__ W1,
                       const float* __restrict__ W2,
                       float* __restrict__ y,
                       float* __restrict__ convz, int N)
{
    __shared__ float W0s[1024], W1s[1024], W2s[1024];
    __shared__ float xs[8][DIM];
    int t = threadIdx.x;
    for (int i = t; i < 1024; i += blockDim.x) { W0s[i]=W0[i]; W1s[i]=W1[i]; W2s[i]=W2[i]; }
    __syncthreads();

    int wid = t >> 5, j = t & 31;
    int nwarps = (blockDim.x >> 5) * gridDim.x;
    const float4 z = make_float4(0.f, 0.f, 0.f, 0.f);
    for (int n = blockIdx.x * 8 + wid; n < N; n += nwarps) {
        const float* xr = x + (size_t)n * DIM;
        #pragma unroll
        for (int q = 0; q < 9; q++) xs[wid][j + 32*q] = xr[j + 32*q];

        float4* cz = (float4*)(convz + (size_t)n * DIM);
        cz[j] = z; cz[j + 32] = z;
        if (j < 8) cz[j + 64] = z;
        __syncwarp();

        float y0 = 0.f;
        #pragma unroll
        for (int i = 0; i < 32; i++) y0 = fmaf(xs[wid][i], W0s[i*32+j], y0);

        float y1[3] = {0.f,0.f,0.f};
        #pragma unroll
        for (int i = 0; i < 32; i++) {
            float w = W1s[i*32+j];
            #pragma unroll
            for (int c = 0; c < 3; c++) y1[c] = fmaf(xs[wid][32+3*i+c], w, y1[c]);
        }
        float y2[5] = {0.f,0.f,0.f,0.f,0.f};
        #pragma unroll
        for (int i = 0; i < 32; i++) {
            float w = W2s[i*32+j];
            #pragma unroll
            for (int c = 0; c < 5; c++) y2[c] = fmaf(xs[wid][128+5*i+c], w, y2[c]);
        }
        float* yr = y + (size_t)n * DIM;
        yr[j] = y0;
        #pragma unroll
        for (int c = 0; c < 3; c++) yr[32+3*j+c] = y1[c];
        #pragma unroll
        for (int c = 0; c < 5; c++) yr[128+5*j+c] = y2[c];
        __syncwarp();
    }
}

// ---------------------------------------------------------------------------
// Kernel 2: edge conv — batched register gathers + tf32 MMA + scalar red
// ---------------------------------------------------------------------------
__device__ __forceinline__ void mma_tf32(float& d0, float& d1, float& d2, float& d3,
                                         unsigned a0, unsigned a1, unsigned a2, unsigned a3,
                                         unsigned b0, unsigned b1)
{
    asm("mma.sync.aligned.m16n8k8.row.col.f32.tf32.tf32.f32 "
        "{%0,%1,%2,%3}, {%4,%5,%6,%7}, {%8,%9}, {%0,%1,%2,%3};"
        : "+f"(d0), "+f"(d1), "+f"(d2), "+f"(d3)
        : "r"(a0), "r"(a1), "r"(a2), "r"(a3), "r"(b0), "r"(b1));
}

__device__ __forceinline__ void red_f32(float* p, float v) {
    asm volatile("red.global.add.f32 [%0], %1;" :: "l"(p), "f"(v) : "memory");
}

__global__ void __launch_bounds__(256, 2) k_edge(
    const float* __restrict__ si1, const float* __restrict__ pos,
    const int* __restrict__ edge_index,      // int32 (JAX x64 disabled)
    const float* __restrict__ Wr1, const float* __restrict__ br1,
    float* __restrict__ conv, int E)
{
    extern __shared__ float sm[];
    float* h_sm  = sm;                             // 64*68 = 4352 (tf32 bits)
    float* w_sm  = h_sm + TILE_E * HSTR;           // 64*228 = 14592
    float* u_sm  = w_sm + TILE_E * WSTR;           // 192
    float* y2_sm = u_sm + 3 * TILE_E;              // 320
    int*   src_sm = (int*)(y2_sm + 5 * TILE_E);    // 64
    int*   dst_sm = src_sm + TILE_E;               // 64
    float* Wr1s  = (float*)(dst_sm + TILE_E);      // 512
    float* br1s  = Wr1s + NRBF * HID;              // 64

    int t = threadIdx.x;
    for (int i = t; i < NRBF * HID; i += 256) Wr1s[i] = Wr1[i];
    if (t < HID) br1s[t] = br1[t];
    __syncthreads();

    const int j  = t & 31;   // lane
    const int g  = t >> 5;   // warp id (8 warps)
    const int e1 = t & 63;   // phase-1 edge within tile
    const int q  = t >> 6;   // phase-1 k-group (0..3)
    const int r4 = j >> 2;
    const int c4 = j & 3;
    const int msb = g & 3;   // phase-2 m-slab (16 edges)
    const int nh = g >> 2;   // n half (112 cols)
    const float rbf_step = 5.0f / 7.0f;

    const uint2* Bfrag = g_Bfrag;

    int ntiles = (E + TILE_E - 1) / TILE_E;
    for (int tile = blockIdx.x; tile < ntiles; tile += gridDim.x) {
        int base = tile * TILE_E;

        // -------- phase 1: geometry, RBF, hidden layer h (tf32) --------
        {
            int eg = base + e1;
            unsigned hx[16];
            if (eg < E) {
                int s = edge_index[eg];
                int d = edge_index[(size_t)E + eg];
                float rx = pos[s*3+0] - pos[d*3+0];
                float ry = pos[s*3+1] - pos[d*3+1];
                float rz = pos[s*3+2] - pos[d*3+2];
                float dd = sqrtf(fmaf(rx,rx, fmaf(ry,ry, rz*rz)) + 1e-12f);
                float inv = 1.f / dd;
                float ux = rx*inv, uy = ry*inv, uz = rz*inv;
                float rbf[8];
                #pragma unroll
                for (int r = 0; r < 8; r++) {
                    float dr = dd - rbf_step * (float)r;
                    rbf[r] = __expf(-dr * dr);
                }
                #pragma unroll
                for (int m = 0; m < 16; m++) {
                    int k = q * 16 + m;
                    float a = br1s[k];
                    #pragma unroll
                    for (int r = 0; r < 8; r++) a = fmaf(rbf[r], Wr1s[r*HID + k], a);
                    hx[m] = cvt_tf32(a / (1.f + __expf(-a)));   // silu -> tf32
                }
                if (q == 0) {
                    u_sm[0*TILE_E+e1] = ux; u_sm[1*TILE_E+e1] = uy; u_sm[2*TILE_E+e1] = uz;
                    y2_sm[0*TILE_E+e1] = ux*uy;
                    y2_sm[1*TILE_E+e1] = uy*uz;
                    y2_sm[2*TILE_E+e1] = (3.f*uz*uz - 1.f) * 0.2886751345948129f;
                    y2_sm[3*TILE_E+e1] = ux*uz;
                    y2_sm[4*TILE_E+e1] = (ux*ux - uy*uy) * 0.5f;
                    src_sm[e1] = s;
                    dst_sm[e1] = d;
                }
            } else {
                #pragma unroll
                for (int m = 0; m < 16; m++) hx[m] = 0u;
                if (q == 0) {
                    #pragma unroll
                    for (int c = 0; c < 3; c++) u_sm[c*TILE_E+e1] = 0.f;
                    #pragma unroll
                    for (int c = 0; c < 5; c++) y2_sm[c*TILE_E+e1] = 0.f;
                    src_sm[e1] = 0; dst_sm[e1] = -1;
                }
            }
            #pragma unroll
            for (int v = 0; v < 4; v++) {
                uint4 pk = make_uint4(hx[4*v+0], hx[4*v+1], hx[4*v+2], hx[4*v+3]);
                *(uint4*)&h_sm[e1*HSTR + q*16 + 4*v] = pk;
            }
        }
        __syncthreads();

        // -------- phase 2: w = h @ Wr2 via tf32 mma.m16n8k8 --------
        {
            float acc[14][4];
            #pragma unroll
            for (int nt = 0; nt < 14; nt++) {
                #pragma unroll
                for (int i = 0; i < 4; i++) acc[nt][i] = 0.f;
            }
            const int arow = msb*16 + r4;
            #pragma unroll 2
            for (int ks = 0; ks < 8; ks++) {
                unsigned a0 = __float_as_uint(h_sm[ arow    *HSTR + ks*8 + c4    ]);
                unsigned a1 = __float_as_uint(h_sm[(arow+8)*HSTR + ks*8 + c4    ]);
                unsigned a2 = __float_as_uint(h_sm[ arow    *HSTR + ks*8 + c4 + 4]);
                unsigned a3 = __float_as_uint(h_sm[(arow+8)*HSTR + ks*8 + c4 + 4]);
                #pragma unroll
                for (int nt = 0; nt < 14; nt++) {
                    int ntg = nh*14 + nt;
                    uint2 b = __ldg(&Bfrag[(ntg*8 + ks)*32 + j]);
                    mma_tf32(acc[nt][0], acc[nt][1], acc[nt][2], acc[nt][3],
                             a0, a1, a2, a3, b.x, b.y);
                }
            }
            #pragma unroll
            for (int nt = 0; nt < 14; nt++) {
                int col = nh*112 + nt*8 + 2*c4;
                int row = msb*16 + r4;
                *(float2*)&w_sm[ row    *WSTR + col] = make_float2(acc[nt][0], acc[nt][1]);
                *(float2*)&w_sm[(row+8)*WSTR + col] = make_float2(acc[nt][2], acc[nt][3]);
            }
        }
        __syncthreads();

        // -------- phase 3: batch-4 register gathers, compute, scalar red --------
        {
            const int ebase = g * 8;
            #pragma unroll
            for (int half = 0; half < 2; half++) {
                float xb[4][9];
                // issue all 36 gather loads (independent; ~high MLP)
                #pragma unroll
                for (int es = 0; es < 4; es++) {
                    int e = ebase + half * 4 + es;
                    if (base + e < E) {
                        const float* xr = si1 + (size_t)src_sm[e] * DIM;
                        xb[es][0] = xr[j];
                        #pragma unroll
                        for (int c = 0; c < 3; c++) xb[es][1+c] = xr[32 + 3*j + c];
                        #pragma unroll
                        for (int c = 0; c < 5; c++) xb[es][4+c] = xr[128 + 5*j + c];
                    }
                }
                // consume
                #pragma unroll
                for (int es = 0; es < 4; es++) {
                    int e = ebase + half * 4 + es;
                    if (base + e < E) {
                        float w[7];
                        #pragma unroll
                        for (int p = 0; p < 7; p++) w[p] = w_sm[e*WSTR + p*32 + j];
                        float uu[3], yy[5];
                        #pragma unroll
                        for (int c = 0; c < 3; c++) uu[c] = u_sm[c*TILE_E + e];
                        #pragma unroll
                        for (int c = 0; c < 5; c++) yy[c] = y2_sm[c*TILE_E + e];

                        float x0 = xb[es][0];
                        float t1 = fmaf(xb[es][1], uu[0],
                                   fmaf(xb[es][2], uu[1], xb[es][3]*uu[2]));
                        float t2 = xb[es][4]*yy[0];
                        #pragma unroll
                        for (int c = 1; c < 5; c++) t2 = fmaf(xb[es][4+c], yy[c], t2);

                        float m0 = fmaf(w[0], x0, fmaf(w[4], t1, w[6]*t2));
                        float a3 = w[3] * x0;
                        float a5 = w[5] * x0;

                        float* db = conv + (size_t)dst_sm[e] * DIM;
                        red_f32(db + j, m0);
                        #pragma unroll
                        for (int c = 0; c < 3; c++)
                            red_f32(db + 32 + 3*j + c, fmaf(w[1], xb[es][1+c], a3*uu[c]));
                        #pragma unroll
                        for (int c = 0; c < 5; c++)
                            red_f32(db + 128 + 5*j + c, fmaf(w[2], xb[es][4+c], a5*yy[c]));
                    }
                }
            }
        }
        __syncthreads();
    }
}

// ---------------------------------------------------------------------------
// Kernel 3: out = gate(nodes + irreps_linear(conv))
// ---------------------------------------------------------------------------
__global__ void k_lin2_gate(const float* __restrict__ conv,
                            const float* __restrict__ nodes,
                            const float* __restrict__ W0,
                            const float* __restrict__ W1,
                            const float* __restrict__ W2,
                            const float* __restrict__ Wg,
                            float* __restrict__ out, int N)
{
    __shared__ float W0s[1024], W1s[1024], W2s[1024], Wgs[2048];
    __shared__ float xs[8][DIM];
    __shared__ float m0s[8][32];
    int t = threadIdx.x;
    for (int i = t; i < 1024; i += blockDim.x) { W0s[i]=W0[i]; W1s[i]=W1[i]; W2s[i]=W2[i]; }
    for (int i = t; i < 2048; i += blockDim.x) Wgs[i] = Wg[i];
    __syncthreads();

    int wid = t >> 5, j = t & 31;
    int nwarps = (blockDim.x >> 5) * gridDim.x;
    for (int n = blockIdx.x * 8 + wid; n < N; n += nwarps) {
        const float* cr = conv + (size_t)n * DIM;
        const float* nr = nodes + (size_t)n * DIM;
        #pragma unroll
        for (int q = 0; q < 9; q++) xs[wid][j + 32*q] = cr[j + 32*q];
        __syncwarp();

        float y0 = nr[j];
        #pragma unroll
        for (int i = 0; i < 32; i++) y0 = fmaf(xs[wid][i], W0s[i*32+j], y0);
        m0s[wid][j] = y0;
        __syncwarp();

        float ga = 0.f, gb = 0.f;
        #pragma unroll
        for (int i = 0; i < 32; i++) {
            float mi = m0s[wid][i];
            ga = fmaf(mi, Wgs[i*64 + j],      ga);
            gb = fmaf(mi, Wgs[i*64 + 32 + j], gb);
        }
        ga = 1.f / (1.f + __expf(-ga));
        gb = 1.f / (1.f + __expf(-gb));

        float y1[3];
        #pragma unroll
        for (int c = 0; c < 3; c++) y1[c] = nr[32 + 3*j + c];
        #pragma unroll
        for (int i = 0; i < 32; i++) {
            float w = W1s[i*32+j];
            #pragma unroll
            for (int c = 0; c < 3; c++) y1[c] = fmaf(xs[wid][32+3*i+c], w, y1[c]);
        }
        float y2[5];
        #pragma unroll
        for (int c = 0; c < 5; c++) y2[c] = nr[128 + 5*j + c];
        #pragma unroll
        for (int i = 0; i < 32; i++) {
            float w = W2s[i*32+j];
            #pragma unroll
            for (int c = 0; c < 5; c++) y2[c] = fmaf(xs[wid][128+5*i+c], w, y2[c]);
        }

        float* yr = out + (size_t)n * DIM;
        yr[j] = y0 / (1.f + __expf(-y0));     // silu
        #pragma unroll
        for (int c = 0; c < 3; c++) yr[32 + 3*j + c] = y1[c] * ga;
        #pragma unroll
        for (int c = 0; c < 5; c++) yr[128 + 5*j + c] = y2[c] * gb;
        __syncwarp();
    }
}

// ---------------------------------------------------------------------------
extern "C" void kernel_launch(void* const* d_in, const int* in_sizes, int n_in,
                              void* d_out, int out_size)
{
    const float* nodes = (const float*)d_in[0];
    const float* pos   = (const float*)d_in[1];
    const float* W0    = (const float*)d_in[2];
    const float* W1    = (const float*)d_in[3];
    const float* W2    = (const float*)d_in[4];
    const float* Wr1   = (const float*)d_in[5];
    const float* br1   = (const float*)d_in[6];
    const float* Wr2   = (const float*)d_in[7];
    const float* Wg    = (const float*)d_in[8];
    const int* edge_index = (const int*)d_in[10];   // int32: JAX x64 disabled
    float* out = (float*)d_out;

    int N = in_sizes[0] / DIM;
    int E = in_sizes[10] / 2;

    float *si1p, *convp;
    cudaGetSymbolAddress((void**)&si1p, g_si1);
    cudaGetSymbolAddress((void**)&convp, g_conv);

    k_prep<<<28, 256>>>(Wr2);
    int nblocks = (N + 7) / 8;
    if (nblocks > 2048) nblocks = 2048;
    k_lin1<<<nblocks, 256>>>(nodes, W0, W1, W2, si1p, convp, N);

    // dynamic shared floats:
    //   h 4352 + w 14592 + u 192 + y2 320 + idx 128 + Wr1 512 + br1 64 = 20160
    const int SMEM_FLOATS = TILE_E*HSTR + TILE_E*WSTR + 3*TILE_E + 5*TILE_E
                          + 2*TILE_E + NRBF*HID + HID;
    const int SMEM = SMEM_FLOATS * 4;   // 80640 bytes -> occupancy 2
    cudaFuncSetAttribute(k_edge, cudaFuncAttributeMaxDynamicSharedMemorySize, SMEM);
    k_edge<<<592, 256, SMEM>>>(si1p, pos, edge_index, Wr1, br1, convp, E);

    k_lin2_gate<<<nblocks, 256>>>(convp, nodes, W0, W1, W2, Wg, out, N);
}

// round 7
// speedup vs baseline: 1.4602x; 1.4602x over previous
#include <cuda_runtime.h>
#include <cstdint>

#define L0 32
#define DIM 288          // 32 + 96 + 160
#define NRBF 8
#define HID 64
#define NPATHS 7
#define WCOLS 224        // NPATHS * L0
#define NORM 0.25f       // 1/sqrt(16)
#define NMAX 50176
#define TILE_E 64
#define HSTR 68          // h_sm row stride (conflict-free A-frag LDS)
#define WSTR 228         // w_sm row stride

// Scratch (static device globals; no runtime allocation allowed)
__device__ float g_si1[(size_t)NMAX * DIM];
__device__ float g_conv[(size_t)NMAX * DIM];
// Wr2 tf32, mma-fragment order, 2 k-steps packed per uint4:
// [(ntg*4 + kp)*32 + lane] -> {ks0.b0, ks0.b1, ks1.b0, ks1.b1}
__device__ uint4 g_Bfrag4[28 * 4 * 32];

__device__ __forceinline__ unsigned cvt_tf32(float v) {
    unsigned r;
    asm("cvt.rna.tf32.f32 %0, %1;" : "=r"(r) : "f"(v));
    return r;
}

// ---------------------------------------------------------------------------
// Kernel 0: build tf32 fragment-ordered Wr2 (pre-scaled by NORM), k-pair packed
// ---------------------------------------------------------------------------
__global__ void k_prep(const float* __restrict__ Wr2)
{
    int ntg = blockIdx.x;            // 0..27 (n-tile of 8 cols)
    int t = threadIdx.x;             // 128 threads: kp = t>>5, lane = t&31
    int kp = t >> 5;                 // 0..3 (k-step pair)
    int lane = t & 31;
    int r4 = lane >> 2, c4 = lane & 3;
    int col = ntg * 8 + r4;
    int ks0 = 2 * kp, ks1 = 2 * kp + 1;
    uint4 b;
    b.x = cvt_tf32(Wr2[(ks0 * 8 + c4)     * WCOLS + col] * NORM);
    b.y = cvt_tf32(Wr2[(ks0 * 8 + c4 + 4) * WCOLS + col] * NORM);
    b.z = cvt_tf32(Wr2[(ks1 * 8 + c4)     * WCOLS + col] * NORM);
    b.w = cvt_tf32(Wr2[(ks1 * 8 + c4 + 4) * WCOLS + col] * NORM);
    g_Bfrag4[(ntg * 4 + kp) * 32 + lane] = b;
}

// ---------------------------------------------------------------------------
// Kernel 1: si1 = irreps_linear(nodes); also zeroes g_conv rows
// ---------------------------------------------------------------------------
__global__ void k_lin1(const float* __restrict__ x,
                       const float* __restrict__ W0,
                       const float* __restrict__ W1,
                       const float* __restrict__ W2,
                       float* __restrict__ y,
                       float* __restrict__ convz, int N)
{
    __shared__ float W0s[1024], W1s[1024], W2s[1024];
    __shared__ float xs[8][DIM];
    int t = threadIdx.x;
    for (int i = t; i < 1024; i += blockDim.x) { W0s[i]=W0[i]; W1s[i]=W1[i]; W2s[i]=W2[i]; }
    __syncthreads();

    int wid = t >> 5, j = t & 31;
    int nwarps = (blockDim.x >> 5) * gridDim.x;
    const float4 z = make_float4(0.f, 0.f, 0.f, 0.f);
    for (int n = blockIdx.x * 8 + wid; n < N; n += nwarps) {
        const float* xr = x + (size_t)n * DIM;
        #pragma unroll
        for (int q = 0; q < 9; q++) xs[wid][j + 32*q] = xr[j + 32*q];

        float4* cz = (float4*)(convz + (size_t)n * DIM);
        cz[j] = z; cz[j + 32] = z;
        if (j < 8) cz[j + 64] = z;
        __syncwarp();

        float y0 = 0.f;
        #pragma unroll
        for (int i = 0; i < 32; i++) y0 = fmaf(xs[wid][i], W0s[i*32+j], y0);

        float y1[3] = {0.f,0.f,0.f};
        #pragma unroll
        for (int i = 0; i < 32; i++) {
            float w = W1s[i*32+j];
            #pragma unroll
            for (int c = 0; c < 3; c++) y1[c] = fmaf(xs[wid][32+3*i+c], w, y1[c]);
        }
        float y2[5] = {0.f,0.f,0.f,0.f,0.f};
        #pragma unroll
        for (int i = 0; i < 32; i++) {
            float w = W2s[i*32+j];
            #pragma unroll
            for (int c = 0; c < 5; c++) y2[c] = fmaf(xs[wid][128+5*i+c], w, y2[c]);
        }
        float* yr = y + (size_t)n * DIM;
        yr[j] = y0;
        #pragma unroll
        for (int c = 0; c < 3; c++) yr[32+3*j+c] = y1[c];
        #pragma unroll
        for (int c = 0; c < 5; c++) yr[128+5*j+c] = y2[c];
        __syncwarp();
    }
}

// ---------------------------------------------------------------------------
// Kernel 2: edge conv — vector gathers + tf32 MMA (LDG.128 B) + red.v4 scatter
// ---------------------------------------------------------------------------
__device__ __forceinline__ void mma_tf32(float& d0, float& d1, float& d2, float& d3,
                                         unsigned a0, unsigned a1, unsigned a2, unsigned a3,
                                         unsigned b0, unsigned b1)
{
    asm("mma.sync.aligned.m16n8k8.row.col.f32.tf32.tf32.f32 "
        "{%0,%1,%2,%3}, {%4,%5,%6,%7}, {%8,%9}, {%0,%1,%2,%3};"
        : "+f"(d0), "+f"(d1), "+f"(d2), "+f"(d3)
        : "r"(a0), "r"(a1), "r"(a2), "r"(a3), "r"(b0), "r"(b1));
}

__device__ __forceinline__ void flush_acc(float* __restrict__ conv, int dstn,
                                          float* __restrict__ ms_stage, int j,
                                          float a0, const float* a1, const float* a2)
{
    ms_stage[j] = a0;
    #pragma unroll
    for (int c = 0; c < 3; c++) ms_stage[32 + 3*j + c] = a1[c];
    #pragma unroll
    for (int c = 0; c < 5; c++) ms_stage[128 + 5*j + c] = a2[c];
    __syncwarp();
    float* db = conv + (size_t)dstn * DIM;
    float4 v0 = *(float4*)&ms_stage[j * 4];
    asm volatile("red.global.add.v4.f32 [%0], {%1,%2,%3,%4};"
                 :: "l"(db + j*4), "f"(v0.x), "f"(v0.y), "f"(v0.z), "f"(v0.w) : "memory");
    float4 v1 = *(float4*)&ms_stage[(j + 32) * 4];
    asm volatile("red.global.add.v4.f32 [%0], {%1,%2,%3,%4};"
                 :: "l"(db + (j+32)*4), "f"(v1.x), "f"(v1.y), "f"(v1.z), "f"(v1.w) : "memory");
    if (j < 8) {
        float4 v2 = *(float4*)&ms_stage[(j + 64) * 4];
        asm volatile("red.global.add.v4.f32 [%0], {%1,%2,%3,%4};"
                     :: "l"(db + (j+64)*4), "f"(v2.x), "f"(v2.y), "f"(v2.z), "f"(v2.w) : "memory");
    }
    __syncwarp();
}

__global__ void __launch_bounds__(256, 2) k_edge(
    const float* __restrict__ si1, const float* __restrict__ pos,
    const int* __restrict__ edge_index,      // int32 (JAX x64 disabled)
    const float* __restrict__ Wr1, const float* __restrict__ br1,
    float* __restrict__ conv, int E)
{
    extern __shared__ float sm[];
    float* h_sm  = sm;                             // 64*68 = 4352 (tf32 bits)
    float* w_sm  = h_sm + TILE_E * HSTR;           // 64*228 = 14592
    float* xst   = w_sm + TILE_E * WSTR;           // 8 warps * 2 * 288 = 4608
    float* u_sm  = xst + 8 * 2 * DIM;              // 192
    float* y2_sm = u_sm + 3 * TILE_E;              // 320
    int*   src_sm = (int*)(y2_sm + 5 * TILE_E);    // 64
    int*   dst_sm = src_sm + TILE_E;               // 64
    float* m_sm  = (float*)(dst_sm + TILE_E);      // 8*292
    float* Wr1s  = m_sm + 8 * 292;                 // 512
    float* br1s  = Wr1s + NRBF * HID;              // 64

    int t = threadIdx.x;
    for (int i = t; i < NRBF * HID; i += 256) Wr1s[i] = Wr1[i];
    if (t < HID) br1s[t] = br1[t];
    __syncthreads();

    const int j  = t & 31;   // lane
    const int g  = t >> 5;   // warp id (8 warps)
    const int e1 = t & 63;   // phase-1 edge within tile
    const int q  = t >> 6;   // phase-1 k-group (0..3)
    const int r4 = j >> 2;
    const int c4 = j & 3;
    const int msb = g & 1;   // phase-2 m-slab (32 edges)
    const int nq = g >> 1;   // phase-2 n-quarter (56 cols = 7 n8-tiles)
    const float rbf_step = 5.0f / 7.0f;

    const uint4* Bfrag = g_Bfrag4;

    int ntiles = (E + TILE_E - 1) / TILE_E;
    for (int tile = blockIdx.x; tile < ntiles; tile += gridDim.x) {
        int base = tile * TILE_E;

        // -------- phase 1: geometry, RBF, hidden layer h (tf32) --------
        {
            int eg = base + e1;
            unsigned hx[16];
            if (eg < E) {
                int s = edge_index[eg];
                int d = edge_index[(size_t)E + eg];
                float rx = pos[s*3+0] - pos[d*3+0];
                float ry = pos[s*3+1] - pos[d*3+1];
                float rz = pos[s*3+2] - pos[d*3+2];
                float dd = sqrtf(fmaf(rx,rx, fmaf(ry,ry, rz*rz)) + 1e-12f);
                float inv = 1.f / dd;
                float ux = rx*inv, uy = ry*inv, uz = rz*inv;
                float rbf[8];
                #pragma unroll
                for (int r = 0; r < 8; r++) {
                    float dr = dd - rbf_step * (float)r;
                    rbf[r] = __expf(-dr * dr);
                }
                #pragma unroll
                for (int m = 0; m < 16; m++) {
                    int k = q * 16 + m;
                    float a = br1s[k];
                    #pragma unroll
                    for (int r = 0; r < 8; r++) a = fmaf(rbf[r], Wr1s[r*HID + k], a);
                    hx[m] = cvt_tf32(a / (1.f + __expf(-a)));   // silu -> tf32
                }
                if (q == 0) {
                    u_sm[0*TILE_E+e1] = ux; u_sm[1*TILE_E+e1] = uy; u_sm[2*TILE_E+e1] = uz;
                    y2_sm[0*TILE_E+e1] = ux*uy;
                    y2_sm[1*TILE_E+e1] = uy*uz;
                    y2_sm[2*TILE_E+e1] = (3.f*uz*uz - 1.f) * 0.2886751345948129f;
                    y2_sm[3*TILE_E+e1] = ux*uz;
                    y2_sm[4*TILE_E+e1] = (ux*ux - uy*uy) * 0.5f;
                    src_sm[e1] = s;
                    dst_sm[e1] = d;
                }
            } else {
                #pragma unroll
                for (int m = 0; m < 16; m++) hx[m] = 0u;
                if (q == 0) {
                    #pragma unroll
                    for (int c = 0; c < 3; c++) u_sm[c*TILE_E+e1] = 0.f;
                    #pragma unroll
                    for (int c = 0; c < 5; c++) y2_sm[c*TILE_E+e1] = 0.f;
                    src_sm[e1] = 0; dst_sm[e1] = 0;
                }
            }
            #pragma unroll
            for (int v = 0; v < 4; v++) {
                uint4 pk = make_uint4(hx[4*v+0], hx[4*v+1], hx[4*v+2], hx[4*v+3]);
                *(uint4*)&h_sm[e1*HSTR + q*16 + 4*v] = pk;
            }
        }
        __syncthreads();

        // -------- phase 2: w = h @ Wr2, 2m x 4n split, LDG.128 B fragments ------
        {
            float acc[2][7][4];
            #pragma unroll
            for (int mt = 0; mt < 2; mt++)
                #pragma unroll
                for (int nt = 0; nt < 7; nt++)
                    #pragma unroll
                    for (int i = 0; i < 4; i++) acc[mt][nt][i] = 0.f;

            #pragma unroll
            for (int kp = 0; kp < 4; kp++) {
                // A fragments for both m16 tiles, both k-steps of the pair
                unsigned af[2][2][4];
                #pragma unroll
                for (int mt = 0; mt < 2; mt++) {
                    int arow = msb*32 + mt*16 + r4;
                    #pragma unroll
                    for (int ks = 0; ks < 2; ks++) {
                        int ko = kp*16 + ks*8;
                        af[mt][ks][0] = __float_as_uint(h_sm[ arow    *HSTR + ko + c4    ]);
                        af[mt][ks][1] = __float_as_uint(h_sm[(arow+8)*HSTR + ko + c4    ]);
                        af[mt][ks][2] = __float_as_uint(h_sm[ arow    *HSTR + ko + c4 + 4]);
                        af[mt][ks][3] = __float_as_uint(h_sm[(arow+8)*HSTR + ko + c4 + 4]);
                    }
                }
                #pragma unroll
                for (int nt = 0; nt < 7; nt++) {
                    int ntg = nq*7 + nt;
                    uint4 b = __ldg(&Bfrag[(ntg*4 + kp)*32 + j]);
                    #pragma unroll
                    for (int mt = 0; mt < 2; mt++) {
                        mma_tf32(acc[mt][nt][0], acc[mt][nt][1], acc[mt][nt][2], acc[mt][nt][3],
                                 af[mt][0][0], af[mt][0][1], af[mt][0][2], af[mt][0][3],
                                 b.x, b.y);
                        mma_tf32(acc[mt][nt][0], acc[mt][nt][1], acc[mt][nt][2], acc[mt][nt][3],
                                 af[mt][1][0], af[mt][1][1], af[mt][1][2], af[mt][1][3],
                                 b.z, b.w);
                    }
                }
            }
            #pragma unroll
            for (int mt = 0; mt < 2; mt++) {
                #pragma unroll
                for (int nt = 0; nt < 7; nt++) {
                    int col = nq*56 + nt*8 + 2*c4;
                    int row = msb*32 + mt*16 + r4;
                    *(float2*)&w_sm[ row    *WSTR + col] = make_float2(acc[mt][nt][0], acc[mt][nt][1]);
                    *(float2*)&w_sm[(row+8)*WSTR + col] = make_float2(acc[mt][nt][2], acc[mt][nt][3]);
                }
            }
        }
        __syncthreads();

        // -------- phase 3: float4 gathers via shared, compute, red.v4 ----------
        {
            const int ebase = g * 8;
            int nvalid = E - base - ebase;
            nvalid = nvalid < 0 ? 0 : (nvalid > 8 ? 8 : nvalid);
            if (nvalid > 0) {
                float* ms_stage = m_sm + g * 292;
                float* xb0 = xst + g * (2 * DIM);

                // prefetch edge 0's si1 row (2.25 LDG.128 per lane)
                const float4* xr4 = (const float4*)(si1 + (size_t)src_sm[ebase] * DIM);
                float4 r0 = xr4[j];
                float4 r1 = xr4[j + 32];
                float4 r2 = make_float4(0.f,0.f,0.f,0.f);
                if (j < 8) r2 = xr4[j + 64];

                #pragma unroll
                for (int es = 0; es < 8; es++) {
                    if (es < nvalid) {
                        float* xb = xb0 + (es & 1) * DIM;
                        ((float4*)xb)[j] = r0;
                        ((float4*)xb)[j + 32] = r1;
                        if (j < 8) ((float4*)xb)[j + 64] = r2;
                        if (es + 1 < nvalid) {
                            const float4* nx = (const float4*)(si1 + (size_t)src_sm[ebase + es + 1] * DIM);
                            r0 = nx[j]; r1 = nx[j + 32];
                            if (j < 8) r2 = nx[j + 64];
                        }
                        __syncwarp();

                        int e = ebase + es;
                        float w[7];
                        #pragma unroll
                        for (int p = 0; p < 7; p++) w[p] = w_sm[e*WSTR + p*32 + j];

                        float x0 = xb[j];
                        float x1v[3], x2v[5];
                        #pragma unroll
                        for (int c = 0; c < 3; c++) x1v[c] = xb[32 + 3*j + c];
                        #pragma unroll
                        for (int c = 0; c < 5; c++) x2v[c] = xb[128 + 5*j + c];
                        float uu[3], yy[5];
                        #pragma unroll
                        for (int c = 0; c < 3; c++) uu[c] = u_sm[c*TILE_E + e];
                        #pragma unroll
                        for (int c = 0; c < 5; c++) yy[c] = y2_sm[c*TILE_E + e];

                        float t1 = fmaf(x1v[0], uu[0], fmaf(x1v[1], uu[1], x1v[2]*uu[2]));
                        float t2 = x2v[0]*yy[0];
                        #pragma unroll
                        for (int c = 1; c < 5; c++) t2 = fmaf(x2v[c], yy[c], t2);

                        float m0 = fmaf(w[0], x0, fmaf(w[4], t1, w[6]*t2));
                        float a3 = w[3] * x0;
                        float a5 = w[5] * x0;
                        float m1[3], m2[5];
                        #pragma unroll
                        for (int c = 0; c < 3; c++) m1[c] = fmaf(w[1], x1v[c], a3*uu[c]);
                        #pragma unroll
                        for (int c = 0; c < 5; c++) m2[c] = fmaf(w[2], x2v[c], a5*yy[c]);

                        flush_acc(conv, dst_sm[e], ms_stage, j, m0, m1, m2);
                    }
                }
            }
        }
        __syncthreads();
    }
}

// ---------------------------------------------------------------------------
// Kernel 3: out = gate(nodes + irreps_linear(conv))
// ---------------------------------------------------------------------------
__global__ void k_lin2_gate(const float* __restrict__ conv,
                            const float* __restrict__ nodes,
                            const float* __restrict__ W0,
                            const float* __restrict__ W1,
                            const float* __restrict__ W2,
                            const float* __restrict__ Wg,
                            float* __restrict__ out, int N)
{
    __shared__ float W0s[1024], W1s[1024], W2s[1024], Wgs[2048];
    __shared__ float xs[8][DIM];
    __shared__ float m0s[8][32];
    int t = threadIdx.x;
    for (int i = t; i < 1024; i += blockDim.x) { W0s[i]=W0[i]; W1s[i]=W1[i]; W2s[i]=W2[i]; }
    for (int i = t; i < 2048; i += blockDim.x) Wgs[i] = Wg[i];
    __syncthreads();

    int wid = t >> 5, j = t & 31;
    int nwarps = (blockDim.x >> 5) * gridDim.x;
    for (int n = blockIdx.x * 8 + wid; n < N; n += nwarps) {
        const float* cr = conv + (size_t)n * DIM;
        const float* nr = nodes + (size_t)n * DIM;
        #pragma unroll
        for (int q = 0; q < 9; q++) xs[wid][j + 32*q] = cr[j + 32*q];
        __syncwarp();

        float y0 = nr[j];
        #pragma unroll
        for (int i = 0; i < 32; i++) y0 = fmaf(xs[wid][i], W0s[i*32+j], y0);
        m0s[wid][j] = y0;
        __syncwarp();

        float ga = 0.f, gb = 0.f;
        #pragma unroll
        for (int i = 0; i < 32; i++) {
            float mi = m0s[wid][i];
            ga = fmaf(mi, Wgs[i*64 + j],      ga);
            gb = fmaf(mi, Wgs[i*64 + 32 + j], gb);
        }
        ga = 1.f / (1.f + __expf(-ga));
        gb = 1.f / (1.f + __expf(-gb));

        float y1[3];
        #pragma unroll
        for (int c = 0; c < 3; c++) y1[c] = nr[32 + 3*j + c];
        #pragma unroll
        for (int i = 0; i < 32; i++) {
            float w = W1s[i*32+j];
            #pragma unroll
            for (int c = 0; c < 3; c++) y1[c] = fmaf(xs[wid][32+3*i+c], w, y1[c]);
        }
        float y2[5];
        #pragma unroll
        for (int c = 0; c < 5; c++) y2[c] = nr[128 + 5*j + c];
        #pragma unroll
        for (int i = 0; i < 32; i++) {
            float w = W2s[i*32+j];
            #pragma unroll
            for (int c = 0; c < 5; c++) y2[c] = fmaf(xs[wid][128+5*i+c], w, y2[c]);
        }

        float* yr = out + (size_t)n * DIM;
        yr[j] = y0 / (1.f + __expf(-y0));     // silu
        #pragma unroll
        for (int c = 0; c < 3; c++) yr[32 + 3*j + c] = y1[c] * ga;
        #pragma unroll
        for (int c = 0; c < 5; c++) yr[128 + 5*j + c] = y2[c] * gb;
        __syncwarp();
    }
}

// ---------------------------------------------------------------------------
extern "C" void kernel_launch(void* const* d_in, const int* in_sizes, int n_in,
                              void* d_out, int out_size)
{
    const float* nodes = (const float*)d_in[0];
    const float* pos   = (const float*)d_in[1];
    const float* W0    = (const float*)d_in[2];
    const float* W1    = (const float*)d_in[3];
    const float* W2    = (const float*)d_in[4];
    const float* Wr1   = (const float*)d_in[5];
    const float* br1   = (const float*)d_in[6];
    const float* Wr2   = (const float*)d_in[7];
    const float* Wg    = (const float*)d_in[8];
    const int* edge_index = (const int*)d_in[10];   // int32: JAX x64 disabled
    float* out = (float*)d_out;

    int N = in_sizes[0] / DIM;
    int E = in_sizes[10] / 2;

    float *si1p, *convp;
    cudaGetSymbolAddress((void**)&si1p, g_si1);
    cudaGetSymbolAddress((void**)&convp, g_conv);

    k_prep<<<28, 128>>>(Wr2);
    int nblocks = (N + 7) / 8;
    if (nblocks > 2048) nblocks = 2048;
    k_lin1<<<nblocks, 256>>>(nodes, W0, W1, W2, si1p, convp, N);

    // dynamic shared floats:
    //   h 4352 + w 14592 + xst 4608 + u 192 + y2 320 + idx 128 + m 2336 + Wr1 512 + br1 64
    const int SMEM_FLOATS = TILE_E*HSTR + TILE_E*WSTR + 8*2*DIM + 3*TILE_E + 5*TILE_E
                          + 2*TILE_E + 8*292 + NRBF*HID + HID;
    const int SMEM = SMEM_FLOATS * 4;   // 108416 bytes -> occupancy 2
    cudaFuncSetAttribute(k_edge, cudaFuncAttributeMaxDynamicSharedMemorySize, SMEM);
    k_edge<<<592, 256, SMEM>>>(si1p, pos, edge_index, Wr1, br1, convp, E);

    k_lin2_gate<<<nblocks, 256>>>(convp, nodes, W0, W1, W2, Wg, out, N);
}

// round 8
// speedup vs baseline: 1.4828x; 1.0155x over previous
#include <cuda_runtime.h>
#include <cstdint>

#define L0 32
#define DIM 288          // 32 + 96 + 160
#define NRBF 8
#define HID 64
#define NPATHS 7
#define WCOLS 224        // NPATHS * L0
#define NORM 0.25f       // 1/sqrt(16)
#define NMAX 50176
#define TILE_E 64
#define HSTR 68          // h_sm row stride (conflict-free A-frag LDS)
#define WSTR 228         // w_sm row stride

// Scratch (static device globals; no runtime allocation allowed)
__device__ float g_si1[(size_t)NMAX * DIM];
__device__ float g_conv[(size_t)NMAX * DIM];
// Wr2 tf32, mma-fragment order, 2 k-steps packed per uint4
__device__ uint4 g_Bfrag4[28 * 4 * 32];

__device__ __forceinline__ unsigned cvt_tf32(float v) {
    unsigned r;
    asm("cvt.rna.tf32.f32 %0, %1;" : "=r"(r) : "f"(v));
    return r;
}

// ---------------------------------------------------------------------------
// Kernel 0: build tf32 fragment-ordered Wr2 (pre-scaled by NORM), k-pair packed
// (idempotent — also reused as a tiny dummy to position k_edge at launch idx 3
//  for the ncu capture window)
// ---------------------------------------------------------------------------
__global__ void k_prep(const float* __restrict__ Wr2)
{
    int ntg = blockIdx.x;            // 0..27 (n-tile of 8 cols)
    int t = threadIdx.x;             // 128 threads: kp = t>>5, lane = t&31
    int kp = t >> 5;                 // 0..3 (k-step pair)
    int lane = t & 31;
    int r4 = lane >> 2, c4 = lane & 3;
    int col = ntg * 8 + r4;
    int ks0 = 2 * kp, ks1 = 2 * kp + 1;
    uint4 b;
    b.x = cvt_tf32(Wr2[(ks0 * 8 + c4)     * WCOLS + col] * NORM);
    b.y = cvt_tf32(Wr2[(ks0 * 8 + c4 + 4) * WCOLS + col] * NORM);
    b.z = cvt_tf32(Wr2[(ks1 * 8 + c4)     * WCOLS + col] * NORM);
    b.w = cvt_tf32(Wr2[(ks1 * 8 + c4 + 4) * WCOLS + col] * NORM);
    g_Bfrag4[(ntg * 4 + kp) * 32 + lane] = b;
}

// ---------------------------------------------------------------------------
// Kernel 1: si1 = irreps_linear(nodes); also zeroes g_conv rows
// ---------------------------------------------------------------------------
__global__ void k_lin1(const float* __restrict__ x,
                       const float* __restrict__ W0,
                       const float* __restrict__ W1,
                       const float* __restrict__ W2,
                       float* __restrict__ y,
                       float* __restrict__ convz, int N)
{
    __shared__ float W0s[1024], W1s[1024], W2s[1024];
    __shared__ float xs[8][DIM];
    int t = threadIdx.x;
    for (int i = t; i < 1024; i += blockDim.x) { W0s[i]=W0[i]; W1s[i]=W1[i]; W2s[i]=W2[i]; }
    __syncthreads();

    int wid = t >> 5, j = t & 31;
    int nwarps = (blockDim.x >> 5) * gridDim.x;
    const float4 z = make_float4(0.f, 0.f, 0.f, 0.f);
    for (int n = blockIdx.x * 8 + wid; n < N; n += nwarps) {
        const float* xr = x + (size_t)n * DIM;
        #pragma unroll
        for (int q = 0; q < 9; q++) xs[wid][j + 32*q] = xr[j + 32*q];

        float4* cz = (float4*)(convz + (size_t)n * DIM);
        cz[j] = z; cz[j + 32] = z;
        if (j < 8) cz[j + 64] = z;
        __syncwarp();

        float y0 = 0.f;
        #pragma unroll
        for (int i = 0; i < 32; i++) y0 = fmaf(xs[wid][i], W0s[i*32+j], y0);

        float y1[3] = {0.f,0.f,0.f};
        #pragma unroll
        for (int i = 0; i < 32; i++) {
            float w = W1s[i*32+j];
            #pragma unroll
            for (int c = 0; c < 3; c++) y1[c] = fmaf(xs[wid][32+3*i+c], w, y1[c]);
        }
        float y2[5] = {0.f,0.f,0.f,0.f,0.f};
        #pragma unroll
        for (int i = 0; i < 32; i++) {
            float w = W2s[i*32+j];
            #pragma unroll
            for (int c = 0; c < 5; c++) y2[c] = fmaf(xs[wid][128+5*i+c], w, y2[c]);
        }
        float* yr = y + (size_t)n * DIM;
        yr[j] = y0;
        #pragma unroll
        for (int c = 0; c < 3; c++) yr[32+3*j+c] = y1[c];
        #pragma unroll
        for (int c = 0; c < 5; c++) yr[128+5*j+c] = y2[c];
        __syncwarp();
    }
}

// ---------------------------------------------------------------------------
// Kernel 2: edge conv — dedup geometry + vector gathers + tf32 MMA + red.v4
// ---------------------------------------------------------------------------
__device__ __forceinline__ void mma_tf32(float& d0, float& d1, float& d2, float& d3,
                                         unsigned a0, unsigned a1, unsigned a2, unsigned a3,
                                         unsigned b0, unsigned b1)
{
    asm("mma.sync.aligned.m16n8k8.row.col.f32.tf32.tf32.f32 "
        "{%0,%1,%2,%3}, {%4,%5,%6,%7}, {%8,%9}, {%0,%1,%2,%3};"
        : "+f"(d0), "+f"(d1), "+f"(d2), "+f"(d3)
        : "r"(a0), "r"(a1), "r"(a2), "r"(a3), "r"(b0), "r"(b1));
}

__device__ __forceinline__ void flush_acc(float* __restrict__ conv, int dstn,
                                          float* __restrict__ ms_stage, int j,
                                          float a0, const float* a1, const float* a2)
{
    ms_stage[j] = a0;
    #pragma unroll
    for (int c = 0; c < 3; c++) ms_stage[32 + 3*j + c] = a1[c];
    #pragma unroll
    for (int c = 0; c < 5; c++) ms_stage[128 + 5*j + c] = a2[c];
    __syncwarp();
    float* db = conv + (size_t)dstn * DIM;
    float4 v0 = *(float4*)&ms_stage[j * 4];
    asm volatile("red.global.add.v4.f32 [%0], {%1,%2,%3,%4};"
                 :: "l"(db + j*4), "f"(v0.x), "f"(v0.y), "f"(v0.z), "f"(v0.w) : "memory");
    float4 v1 = *(float4*)&ms_stage[(j + 32) * 4];
    asm volatile("red.global.add.v4.f32 [%0], {%1,%2,%3,%4};"
                 :: "l"(db + (j+32)*4), "f"(v1.x), "f"(v1.y), "f"(v1.z), "f"(v1.w) : "memory");
    if (j < 8) {
        float4 v2 = *(float4*)&ms_stage[(j + 64) * 4];
        asm volatile("red.global.add.v4.f32 [%0], {%1,%2,%3,%4};"
                     :: "l"(db + (j+64)*4), "f"(v2.x), "f"(v2.y), "f"(v2.z), "f"(v2.w) : "memory");
    }
    __syncwarp();
}

__global__ void __launch_bounds__(256, 2) k_edge(
    const float* __restrict__ si1, const float* __restrict__ pos,
    const int* __restrict__ edge_index,      // int32 (JAX x64 disabled)
    const float* __restrict__ Wr1, const float* __restrict__ br1,
    float* __restrict__ conv, int E)
{
    extern __shared__ float sm[];
    float* h_sm   = sm;                             // 64*68 = 4352 (tf32 bits)
    float* w_sm   = h_sm + TILE_E * HSTR;           // 64*228 = 14592
    float* xst    = w_sm + TILE_E * WSTR;           // 8 warps * 2 * 288 = 4608
    float* rbf_sm = xst + 8 * 2 * DIM;              // 8*64 = 512
    float* u_sm   = rbf_sm + NRBF * TILE_E;         // 192
    float* y2_sm  = u_sm + 3 * TILE_E;              // 320
    int*   src_sm = (int*)(y2_sm + 5 * TILE_E);     // 64
    int*   dst_sm = src_sm + TILE_E;                // 64
    float* m_sm   = (float*)(dst_sm + TILE_E);      // 8*292
    float* Wr1s   = m_sm + 8 * 292;                 // 512
    float* br1s   = Wr1s + NRBF * HID;              // 64

    int t = threadIdx.x;
    for (int i = t; i < NRBF * HID; i += 256) Wr1s[i] = Wr1[i];
    if (t < HID) br1s[t] = br1[t];
    __syncthreads();

    const int j  = t & 31;   // lane
    const int g  = t >> 5;   // warp id (8 warps)
    const int e1 = t & 63;   // phase-1 edge within tile
    const int q  = t >> 6;   // phase-1 k-group (0..3)
    const int r4 = j >> 2;
    const int c4 = j & 3;
    const int msb = g & 1;   // phase-2 m-slab (32 edges)
    const int nq = g >> 1;   // phase-2 n-quarter (56 cols = 7 n8-tiles)
    const float rbf_step = 5.0f / 7.0f;

    const uint4* Bfrag = g_Bfrag4;

    int ntiles = (E + TILE_E - 1) / TILE_E;
    for (int tile = blockIdx.x; tile < ntiles; tile += gridDim.x) {
        int base = tile * TILE_E;

        // -------- phase 1a: geometry, once per edge (threads 0..63) --------
        if (t < TILE_E) {
            int eg = base + t;
            if (eg < E) {
                int s = edge_index[eg];
                int d = edge_index[(size_t)E + eg];
                float rx = pos[s*3+0] - pos[d*3+0];
                float ry = pos[s*3+1] - pos[d*3+1];
                float rz = pos[s*3+2] - pos[d*3+2];
                float dd = sqrtf(fmaf(rx,rx, fmaf(ry,ry, rz*rz)) + 1e-12f);
                float inv = 1.f / dd;
                float ux = rx*inv, uy = ry*inv, uz = rz*inv;
                #pragma unroll
                for (int r = 0; r < 8; r++) {
                    float dr = dd - rbf_step * (float)r;
                    rbf_sm[r*TILE_E + t] = __expf(-dr * dr);
                }
                u_sm[0*TILE_E+t] = ux; u_sm[1*TILE_E+t] = uy; u_sm[2*TILE_E+t] = uz;
                y2_sm[0*TILE_E+t] = ux*uy;
                y2_sm[1*TILE_E+t] = uy*uz;
                y2_sm[2*TILE_E+t] = (3.f*uz*uz - 1.f) * 0.2886751345948129f;
                y2_sm[3*TILE_E+t] = ux*uz;
                y2_sm[4*TILE_E+t] = (ux*ux - uy*uy) * 0.5f;
                src_sm[t] = s;
                dst_sm[t] = d;
            } else {
                #pragma unroll
                for (int r = 0; r < 8; r++) rbf_sm[r*TILE_E + t] = 0.f;
                #pragma unroll
                for (int c = 0; c < 3; c++) u_sm[c*TILE_E+t] = 0.f;
                #pragma unroll
                for (int c = 0; c < 5; c++) y2_sm[c*TILE_E+t] = 0.f;
                src_sm[t] = 0; dst_sm[t] = 0;
            }
        }
        __syncthreads();

        // -------- phase 1b: hidden layer h (tf32), all 256 threads --------
        {
            float rbf[8];
            #pragma unroll
            for (int r = 0; r < 8; r++) rbf[r] = rbf_sm[r*TILE_E + e1];
            unsigned hx[16];
            #pragma unroll
            for (int m = 0; m < 16; m++) {
                int k = q * 16 + m;
                float a = br1s[k];
                #pragma unroll
                for (int r = 0; r < 8; r++) a = fmaf(rbf[r], Wr1s[r*HID + k], a);
                hx[m] = cvt_tf32(a / (1.f + __expf(-a)));   // silu -> tf32
            }
            #pragma unroll
            for (int v = 0; v < 4; v++) {
                uint4 pk = make_uint4(hx[4*v+0], hx[4*v+1], hx[4*v+2], hx[4*v+3]);
                *(uint4*)&h_sm[e1*HSTR + q*16 + 4*v] = pk;
            }
        }
        __syncthreads();

        // -------- phase 2: w = h @ Wr2, 2m x 4n split, LDG.128 B fragments ------
        {
            float acc[2][7][4];
            #pragma unroll
            for (int mt = 0; mt < 2; mt++)
                #pragma unroll
                for (int nt = 0; nt < 7; nt++)
                    #pragma unroll
                    for (int i = 0; i < 4; i++) acc[mt][nt][i] = 0.f;

            #pragma unroll
            for (int kp = 0; kp < 4; kp++) {
                unsigned af[2][2][4];
                #pragma unroll
                for (int mt = 0; mt < 2; mt++) {
                    int arow = msb*32 + mt*16 + r4;
                    #pragma unroll
                    for (int ks = 0; ks < 2; ks++) {
                        int ko = kp*16 + ks*8;
                        af[mt][ks][0] = __float_as_uint(h_sm[ arow    *HSTR + ko + c4    ]);
                        af[mt][ks][1] = __float_as_uint(h_sm[(arow+8)*HSTR + ko + c4    ]);
                        af[mt][ks][2] = __float_as_uint(h_sm[ arow    *HSTR + ko + c4 + 4]);
                        af[mt][ks][3] = __float_as_uint(h_sm[(arow+8)*HSTR + ko + c4 + 4]);
                    }
                }
                #pragma unroll
                for (int nt = 0; nt < 7; nt++) {
                    int ntg = nq*7 + nt;
                    uint4 b = __ldg(&Bfrag[(ntg*4 + kp)*32 + j]);
                    #pragma unroll
                    for (int mt = 0; mt < 2; mt++) {
                        mma_tf32(acc[mt][nt][0], acc[mt][nt][1], acc[mt][nt][2], acc[mt][nt][3],
                                 af[mt][0][0], af[mt][0][1], af[mt][0][2], af[mt][0][3],
                                 b.x, b.y);
                        mma_tf32(acc[mt][nt][0], acc[mt][nt][1], acc[mt][nt][2], acc[mt][nt][3],
                                 af[mt][1][0], af[mt][1][1], af[mt][1][2], af[mt][1][3],
                                 b.z, b.w);
                    }
                }
            }
            #pragma unroll
            for (int mt = 0; mt < 2; mt++) {
                #pragma unroll
                for (int nt = 0; nt < 7; nt++) {
                    int col = nq*56 + nt*8 + 2*c4;
                    int row = msb*32 + mt*16 + r4;
                    *(float2*)&w_sm[ row    *WSTR + col] = make_float2(acc[mt][nt][0], acc[mt][nt][1]);
                    *(float2*)&w_sm[(row+8)*WSTR + col] = make_float2(acc[mt][nt][2], acc[mt][nt][3]);
                }
            }
        }
        __syncthreads();

        // -------- phase 3: float4 gathers via shared, compute, red.v4 ----------
        {
            const int ebase = g * 8;
            int nvalid = E - base - ebase;
            nvalid = nvalid < 0 ? 0 : (nvalid > 8 ? 8 : nvalid);
            if (nvalid > 0) {
                float* ms_stage = m_sm + g * 292;
                float* xb0 = xst + g * (2 * DIM);

                const float4* xr4 = (const float4*)(si1 + (size_t)src_sm[ebase] * DIM);
                float4 r0 = xr4[j];
                float4 r1 = xr4[j + 32];
                float4 r2 = make_float4(0.f,0.f,0.f,0.f);
                if (j < 8) r2 = xr4[j + 64];

                #pragma unroll
                for (int es = 0; es < 8; es++) {
                    if (es < nvalid) {
                        float* xb = xb0 + (es & 1) * DIM;
                        ((float4*)xb)[j] = r0;
                        ((float4*)xb)[j + 32] = r1;
                        if (j < 8) ((float4*)xb)[j + 64] = r2;
                        if (es + 1 < nvalid) {
                            const float4* nx = (const float4*)(si1 + (size_t)src_sm[ebase + es + 1] * DIM);
                            r0 = nx[j]; r1 = nx[j + 32];
                            if (j < 8) r2 = nx[j + 64];
                        }
                        __syncwarp();

                        int e = ebase + es;
                        float w[7];
                        #pragma unroll
                        for (int p = 0; p < 7; p++) w[p] = w_sm[e*WSTR + p*32 + j];

                        float x0 = xb[j];
                        float x1v[3], x2v[5];
                        #pragma unroll
                        for (int c = 0; c < 3; c++) x1v[c] = xb[32 + 3*j + c];
                        #pragma unroll
                        for (int c = 0; c < 5; c++) x2v[c] = xb[128 + 5*j + c];
                        float uu[3], yy[5];
                        #pragma unroll
                        for (int c = 0; c < 3; c++) uu[c] = u_sm[c*TILE_E + e];
                        #pragma unroll
                        for (int c = 0; c < 5; c++) yy[c] = y2_sm[c*TILE_E + e];

                        float t1 = fmaf(x1v[0], uu[0], fmaf(x1v[1], uu[1], x1v[2]*uu[2]));
                        float t2 = x2v[0]*yy[0];
                        #pragma unroll
                        for (int c = 1; c < 5; c++) t2 = fmaf(x2v[c], yy[c], t2);

                        float m0 = fmaf(w[0], x0, fmaf(w[4], t1, w[6]*t2));
                        float a3 = w[3] * x0;
                        float a5 = w[5] * x0;
                        float m1[3], m2[5];
                        #pragma unroll
                        for (int c = 0; c < 3; c++) m1[c] = fmaf(w[1], x1v[c], a3*uu[c]);
                        #pragma unroll
                        for (int c = 0; c < 5; c++) m2[c] = fmaf(w[2], x2v[c], a5*yy[c]);

                        flush_acc(conv, dst_sm[e], ms_stage, j, m0, m1, m2);
                    }
                }
            }
        }
        __syncthreads();
    }
}

// ---------------------------------------------------------------------------
// Kernel 3: out = gate(nodes + irreps_linear(conv))
// ---------------------------------------------------------------------------
__global__ void k_lin2_gate(const float* __restrict__ conv,
                            const float* __restrict__ nodes,
                            const float* __restrict__ W0,
                            const float* __restrict__ W1,
                            const float* __restrict__ W2,
                            const float* __restrict__ Wg,
                            float* __restrict__ out, int N)
{
    __shared__ float W0s[1024], W1s[1024], W2s[1024], Wgs[2048];
    __shared__ float xs[8][DIM];
    __shared__ float m0s[8][32];
    int t = threadIdx.x;
    for (int i = t; i < 1024; i += blockDim.x) { W0s[i]=W0[i]; W1s[i]=W1[i]; W2s[i]=W2[i]; }
    for (int i = t; i < 2048; i += blockDim.x) Wgs[i] = Wg[i];
    __syncthreads();

    int wid = t >> 5, j = t & 31;
    int nwarps = (blockDim.x >> 5) * gridDim.x;
    for (int n = blockIdx.x * 8 + wid; n < N; n += nwarps) {
        const float* cr = conv + (size_t)n * DIM;
        const float* nr = nodes + (size_t)n * DIM;
        #pragma unroll
        for (int q = 0; q < 9; q++) xs[wid][j + 32*q] = cr[j + 32*q];
        __syncwarp();

        float y0 = nr[j];
        #pragma unroll
        for (int i = 0; i < 32; i++) y0 = fmaf(xs[wid][i], W0s[i*32+j], y0);
        m0s[wid][j] = y0;
        __syncwarp();

        float ga = 0.f, gb = 0.f;
        #pragma unroll
        for (int i = 0; i < 32; i++) {
            float mi = m0s[wid][i];
            ga = fmaf(mi, Wgs[i*64 + j],      ga);
            gb = fmaf(mi, Wgs[i*64 + 32 + j], gb);
        }
        ga = 1.f / (1.f + __expf(-ga));
        gb = 1.f / (1.f + __expf(-gb));

        float y1[3];
        #pragma unroll
        for (int c = 0; c < 3; c++) y1[c] = nr[32 + 3*j + c];
        #pragma unroll
        for (int i = 0; i < 32; i++) {
            float w = W1s[i*32+j];
            #pragma unroll
            for (int c = 0; c < 3; c++) y1[c] = fmaf(xs[wid][32+3*i+c], w, y1[c]);
        }
        float y2[5];
        #pragma unroll
        for (int c = 0; c < 5; c++) y2[c] = nr[128 + 5*j + c];
        #pragma unroll
        for (int i = 0; i < 32; i++) {
            float w = W2s[i*32+j];
            #pragma unroll
            for (int c = 0; c < 5; c++) y2[c] = fmaf(xs[wid][128+5*i+c], w, y2[c]);
        }

        float* yr = out + (size_t)n * DIM;
        yr[j] = y0 / (1.f + __expf(-y0));     // silu
        #pragma unroll
        for (int c = 0; c < 3; c++) yr[32 + 3*j + c] = y1[c] * ga;
        #pragma unroll
        for (int c = 0; c < 5; c++) yr[128 + 5*j + c] = y2[c] * gb;
        __syncwarp();
    }
}

// ---------------------------------------------------------------------------
extern "C" void kernel_launch(void* const* d_in, const int* in_sizes, int n_in,
                              void* d_out, int out_size)
{
    const float* nodes = (const float*)d_in[0];
    const float* pos   = (const float*)d_in[1];
    const float* W0    = (const float*)d_in[2];
    const float* W1    = (const float*)d_in[3];
    const float* W2    = (const float*)d_in[4];
    const float* Wr1   = (const float*)d_in[5];
    const float* br1   = (const float*)d_in[6];
    const float* Wr2   = (const float*)d_in[7];
    const float* Wg    = (const float*)d_in[8];
    const int* edge_index = (const int*)d_in[10];   // int32: JAX x64 disabled
    float* out = (float*)d_out;

    int N = in_sizes[0] / DIM;
    int E = in_sizes[10] / 2;

    float *si1p, *convp;
    cudaGetSymbolAddress((void**)&si1p, g_si1);
    cudaGetSymbolAddress((void**)&convp, g_conv);

    int nblocks = (N + 7) / 8;
    if (nblocks > 2048) nblocks = 2048;

    k_prep<<<28, 128>>>(Wr2);                                       // kernel 0
    k_lin1<<<nblocks, 256>>>(nodes, W0, W1, W2, si1p, convp, N);    // kernel 1
    k_prep<<<28, 128>>>(Wr2);   // idempotent dummy — positions k_edge at idx 3
                                // for the ncu -s capture window        kernel 2

    // dynamic shared floats: h 4352 + w 14592 + xst 4608 + rbf 512 + u 192
    //   + y2 320 + idx 128 + m 2336 + Wr1 512 + br1 64 = 27616 -> 110464 B
    const int SMEM_FLOATS = TILE_E*HSTR + TILE_E*WSTR + 8*2*DIM + NRBF*TILE_E
                          + 3*TILE_E + 5*TILE_E + 2*TILE_E + 8*292 + NRBF*HID + HID;
    const int SMEM = SMEM_FLOATS * 4;
    cudaFuncSetAttribute(k_edge, cudaFuncAttributeMaxDynamicSharedMemorySize, SMEM);
    k_edge<<<592, 256, SMEM>>>(si1p, pos, edge_index, Wr1, br1, convp, E);  // kernel 3

    k_lin2_gate<<<nblocks, 256>>>(convp, nodes, W0, W1, W2, Wg, out, N);    // kernel 4
}